// round 15
// baseline (speedup 1.0000x reference)
#include <cuda_runtime.h>
#include <cuda_fp16.h>
#include <cstdint>

// Problem capacities (from reference: N=100000, E=1600000, 128->128->64)
#define MAXN 100000
#define MAXE 1600000

// ---------------- scratch (__device__ globals, 256B-aligned for vector ops) --
__device__ __align__(256) unsigned long long g_hist64[MAXN]; // {cnt:32, deg_fx24:32}
__device__ __align__(256) float  g_dinv[MAXN];
__device__ __align__(256) int    g_cnt[MAXN];
__device__ __align__(256) int    g_cursor[MAXN];
__device__ __align__(256) int    g_off[MAXN + 2];
__device__ __align__(256) unsigned long long g_bstate[256];  // lookback states
__device__ __align__(256) int2   g_epack[MAXE];             // {src, bits(w*dinv[src])}
__device__ __align__(256) __half g_hH [(size_t)MAXN * 128]; // x @ W1   (fp16)
__device__ __align__(256) float  g_h1 [(size_t)MAXN * 128]; // relu(agg1 + b1) fp32
__device__ __align__(256) __half g_h2H[(size_t)MAXN * 64];  // h1 @ W2  (fp16)

// ---------------- init: deg=1 (self loop, fixed-point 2^24), counters=0 ------
__global__ void init_kernel(int n, int e) {
    int i = blockIdx.x * blockDim.x + threadIdx.x;
    if (i == 0) g_off[n] = e;
    if (i < 256) g_bstate[i] = 0ULL;
    if (i < n) {
        g_hist64[i] = (unsigned long long)(1u << 24);  // deg=1.0 fx24, cnt=0
        g_cursor[i] = 0;
    }
}

// ---------------- fused degree+count histogram (single 64-bit atomic) --------
// edge_index is int32 (JAX default x64-disabled downcasts jnp.int64 -> int32).
__global__ void hist_kernel(int e, const int* __restrict__ ei,
                            const float* __restrict__ ew) {
    int i = blockIdx.x * blockDim.x + threadIdx.x;
    if (i >= e) return;
    int c = ei[e + i];                         // col = ei[1][i]
    unsigned wfx = __float2uint_rn(ew[i] * 16777216.0f);   // w * 2^24
    atomicAdd(&g_hist64[c], (1ULL << 32) | (unsigned long long)wfx);
}

// ---------------- single-pass scan, warp-parallel decoupled lookback ---------
// 98 blocks x 256 thr; 1024 elements/block; one wave (98 <= 148 SMs).
// Unpacks hist64 -> cnt + dinv.
__global__ __launch_bounds__(256) void scan_lookback(int n) {
    __shared__ int wsum[8];
    __shared__ int s_prefix;
    int t = threadIdx.x, lane = t & 31, w = t >> 5;
    int bid = blockIdx.x;
    int base = bid * 1024 + t * 4;

    int v[4];
#pragma unroll
    for (int j = 0; j < 4; j++) {
        int idx = base + j;
        if (idx < n) {
            unsigned long long hv = g_hist64[idx];
            v[j] = (int)(hv >> 32);
            g_cnt[idx] = v[j];
            g_dinv[idx] = rsqrtf((float)(unsigned)hv * 5.9604644775390625e-8f); // 2^-24
        } else v[j] = 0;
    }
    int tsum = v[0] + v[1] + v[2] + v[3];

    // warp inclusive scan of per-thread sums
    int sc = tsum;
#pragma unroll
    for (int d = 1; d < 32; d <<= 1) {
        int u = __shfl_up_sync(~0u, sc, d);
        if (lane >= d) sc += u;
    }
    if (lane == 31) wsum[w] = sc;
    __syncthreads();
    if (w == 0) {
        int s = (lane < 8) ? wsum[lane] : 0;
#pragma unroll
        for (int d = 1; d < 8; d <<= 1) {
            int u = __shfl_up_sync(~0u, s, d);
            if (lane >= d) s += u;
        }
        if (lane < 8) wsum[lane] = s;       // inclusive scan of warp sums
    }
    __syncthreads();
    int total = wsum[7];

    // warp 0: publish aggregate, then warp-parallel lookback
    if (w == 0) {
        if (bid == 0) {
            if (lane == 0) {
                atomicExch(&g_bstate[0], (2ULL << 32) | (unsigned)total);
                s_prefix = 0;
            }
        } else {
            if (lane == 0)
                atomicExch(&g_bstate[bid], (1ULL << 32) | (unsigned)total);
            __syncwarp();
            int pre = 0;
            int p = bid - 1;
            while (true) {
                int idx = p - lane;            // lane 0 = nearest predecessor
                unsigned long long st = (idx >= 0)
                    ? atomicAdd(&g_bstate[idx], 0ULL) : (2ULL << 32);
                unsigned flag = (unsigned)(st >> 32);
                unsigned pm = __ballot_sync(~0u, flag == 2);
                unsigned zm = __ballot_sync(~0u, flag == 0);
                int firstP = pm ? (__ffs(pm) - 1) : 32;
                unsigned before = (firstP < 32) ? ((1u << firstP) - 1u) : ~0u;
                if (zm & before) continue;     // pending block blocks the window
                int s;
                if (firstP < 32) {
                    s = (lane <= firstP) ? (int)(unsigned)st : 0;   // aggs + prefix
                } else {
                    if (zm) continue;          // whole window must be ready
                    s = (int)(unsigned)st;     // 32 aggregates
                }
#pragma unroll
                for (int d = 16; d > 0; d >>= 1) s += __shfl_down_sync(~0u, s, d);
                s = __shfl_sync(~0u, s, 0);
                pre += s;
                if (firstP < 32) break;
                p -= 32;
            }
            if (lane == 0) {
                atomicExch(&g_bstate[bid], (2ULL << 32) | (unsigned)(pre + total));
                s_prefix = pre;
            }
        }
    }
    __syncthreads();

    int run = s_prefix + ((w > 0) ? wsum[w - 1] : 0) + (sc - tsum);
#pragma unroll
    for (int j = 0; j < 4; j++) {
        int idx = base + j;
        if (idx < n) g_off[idx] = run;
        run += v[j];
    }
}

// ---------------- scatter edges into CSR buckets -----------------------------
__global__ void scatter_kernel(int e, const int* __restrict__ ei,
                               const float* __restrict__ ew) {
    int i = blockIdx.x * blockDim.x + threadIdx.x;
    if (i >= e) return;
    int r = ei[i];
    int c = ei[e + i];
    int pos = g_off[c] + atomicAdd(&g_cursor[c], 1);
    float sw = ew[i] * g_dinv[r];              // w * d_src^{-1/2}
    g_epack[pos] = make_int2(r, __float_as_int(sw));
}

// ---------------- tf32 tensor-core GEMM: Y[n,OC] = X[n,128] @ W[128,OC] ------
__device__ __forceinline__ uint32_t f2tf(float x) {
    uint32_t r;
    asm("cvt.rna.tf32.f32 %0, %1;" : "=r"(r) : "f"(x));
    return r;
}

__device__ __forceinline__ void mma_tf32(float* c, const uint32_t* a,
                                         uint32_t b0, uint32_t b1) {
    asm volatile(
        "mma.sync.aligned.m16n8k8.row.col.f32.tf32.tf32.f32 "
        "{%0,%1,%2,%3}, {%4,%5,%6,%7}, {%8,%9}, {%0,%1,%2,%3};\n"
        : "+f"(c[0]), "+f"(c[1]), "+f"(c[2]), "+f"(c[3])
        : "r"(a[0]), "r"(a[1]), "r"(a[2]), "r"(a[3]), "r"(b0), "r"(b1));
}

// (round-10 operand path: direct-LDG A — measured fastest)
template <int OC>
__device__ __forceinline__ void gemm_tf32_body(int n, const float* __restrict__ X,
                                               const float* __restrict__ W,
                                               __half* __restrict__ Y) {
    constexpr int K = 128;
    constexpr int KC = 32;           // k-chunk
    constexpr int OCP = OC + 4;      // padded smem row
    constexpr int NT = OC / 8;       // n-tiles of 8
    __shared__ __align__(16) uint32_t Ws[KC * OCP];

    int tid = threadIdx.x;
    int warp = tid >> 5;
    int lane = tid & 31;
    int g  = lane >> 2;              // 0..7
    int tg = lane & 3;               // 0..3
    int rbase = blockIdx.x * 128 + warp * 32;

    float acc[2][NT][4];
#pragma unroll
    for (int t = 0; t < 2; t++)
#pragma unroll
        for (int nt = 0; nt < NT; nt++)
#pragma unroll
            for (int j = 0; j < 4; j++) acc[t][nt][j] = 0.f;

    int ra[2], rb[2];
#pragma unroll
    for (int t = 0; t < 2; t++) {
        ra[t] = min(rbase + t * 16 + g,     n - 1);
        rb[t] = min(rbase + t * 16 + g + 8, n - 1);
    }

    for (int kc = 0; kc < K; kc += KC) {
        for (int i = tid; i < KC * OC / 4; i += 128) {
            int kk = i / (OC / 4);
            int cc = i % (OC / 4);
            float4 v = reinterpret_cast<const float4*>(W + (size_t)(kc + kk) * OC)[cc];
            uint4 tv = make_uint4(f2tf(v.x), f2tf(v.y), f2tf(v.z), f2tf(v.w));
            *reinterpret_cast<uint4*>(&Ws[kk * OCP + cc * 4]) = tv;
        }
        __syncthreads();

#pragma unroll
        for (int ks = 0; ks < KC; ks += 8) {
            int k0 = kc + ks;
            uint32_t a[2][4];
#pragma unroll
            for (int t = 0; t < 2; t++) {
                a[t][0] = f2tf(X[(size_t)ra[t] * K + k0 + tg]);
                a[t][1] = f2tf(X[(size_t)rb[t] * K + k0 + tg]);
                a[t][2] = f2tf(X[(size_t)ra[t] * K + k0 + tg + 4]);
                a[t][3] = f2tf(X[(size_t)rb[t] * K + k0 + tg + 4]);
            }
#pragma unroll
            for (int nt = 0; nt < NT; nt++) {
                uint32_t b0 = Ws[(ks + tg)     * OCP + nt * 8 + g];
                uint32_t b1 = Ws[(ks + tg + 4) * OCP + nt * 8 + g];
                mma_tf32(acc[0][nt], a[0], b0, b1);
                mma_tf32(acc[1][nt], a[1], b0, b1);
            }
        }
        __syncthreads();
    }

#pragma unroll
    for (int t = 0; t < 2; t++) {
        int r0 = rbase + t * 16 + g;
        int r1 = r0 + 8;
#pragma unroll
        for (int nt = 0; nt < NT; nt++) {
            int col = nt * 8 + 2 * tg;
            if (r0 < n)
                *reinterpret_cast<__half2*>(Y + (size_t)r0 * OC + col) =
                    __floats2half2_rn(acc[t][nt][0], acc[t][nt][1]);
            if (r1 < n)
                *reinterpret_cast<__half2*>(Y + (size_t)r1 * OC + col) =
                    __floats2half2_rn(acc[t][nt][2], acc[t][nt][3]);
        }
    }
}

__global__ __launch_bounds__(128) void gemm1_kernel(int n, const float* __restrict__ X,
                                                    const float* __restrict__ W) {
    gemm_tf32_body<128>(n, X, W, g_hH);
}

__global__ __launch_bounds__(128) void gemm2_kernel(int n, const float* __restrict__ W) {
    gemm_tf32_body<64>(n, g_h1, W, g_h2H);
}

// ---------------- aggregation layer 1: TWO warps per node (F=128) ------------
// Each warp covers 64 features (half2 per lane). Gather-only, fp32 accumulate.
__global__ __launch_bounds__(256) void agg1_kernel(int n, const float* __restrict__ b1) {
    int gw = blockIdx.x * 8 + (threadIdx.x >> 5);   // global warp id
    int node = gw >> 1;
    if (node >= n) return;
    int half = gw & 1;
    int lane = threadIdx.x & 31;
    int fofs = half * 64 + lane * 2;                // feature pair offset
    float di = g_dinv[node];

    float2 f = __half22float2(
        *reinterpret_cast<const __half2*>(g_hH + (size_t)node * 128 + fofs));
    float acc0 = di * f.x, acc1 = di * f.y;

    int e0 = g_off[node];
    int e1 = g_off[node + 1];
    int e = e0;
    for (; e + 2 <= e1; e += 2) {
        int2 p0 = g_epack[e];
        int2 p1 = g_epack[e + 1];
        float w0 = __int_as_float(p0.y);
        float w1 = __int_as_float(p1.y);
        float2 a = __half22float2(
            *reinterpret_cast<const __half2*>(g_hH + (size_t)p0.x * 128 + fofs));
        float2 b = __half22float2(
            *reinterpret_cast<const __half2*>(g_hH + (size_t)p1.x * 128 + fofs));
        acc0 = fmaf(w0, a.x, acc0); acc1 = fmaf(w0, a.y, acc1);
        acc0 = fmaf(w1, b.x, acc0); acc1 = fmaf(w1, b.y, acc1);
    }
    if (e < e1) {
        int2 p0 = g_epack[e];
        float w0 = __int_as_float(p0.y);
        float2 a = __half22float2(
            *reinterpret_cast<const __half2*>(g_hH + (size_t)p0.x * 128 + fofs));
        acc0 = fmaf(w0, a.x, acc0); acc1 = fmaf(w0, a.y, acc1);
    }

    float o0 = fmaxf(fmaf(di, acc0, b1[fofs]),     0.f);
    float o1 = fmaxf(fmaf(di, acc1, b1[fofs + 1]), 0.f);
    *reinterpret_cast<float2*>(g_h1 + (size_t)node * 128 + fofs) = make_float2(o0, o1);
}

// ---------------- aggregation layer 2: one warp per node (F=64) --------------
__global__ __launch_bounds__(256) void agg2_kernel(int n, const float* __restrict__ b2,
                                                   float* __restrict__ out) {
    int node = blockIdx.x * 8 + (threadIdx.x >> 5);
    if (node >= n) return;
    int lane = threadIdx.x & 31;
    float di = g_dinv[node];

    float2 f = __half22float2(
        reinterpret_cast<const __half2*>(g_h2H + (size_t)node * 64)[lane]);
    float acc0 = di * f.x, acc1 = di * f.y;

    int e0 = g_off[node];
    int e1 = g_off[node + 1];
    int e = e0;
    for (; e + 2 <= e1; e += 2) {
        int2 p0 = g_epack[e];
        int2 p1 = g_epack[e + 1];
        float w0 = __int_as_float(p0.y);
        float w1 = __int_as_float(p1.y);
        float2 a = __half22float2(
            reinterpret_cast<const __half2*>(g_h2H + (size_t)p0.x * 64)[lane]);
        float2 b = __half22float2(
            reinterpret_cast<const __half2*>(g_h2H + (size_t)p1.x * 64)[lane]);
        acc0 = fmaf(w0, a.x, acc0); acc1 = fmaf(w0, a.y, acc1);
        acc0 = fmaf(w1, b.x, acc0); acc1 = fmaf(w1, b.y, acc1);
    }
    if (e < e1) {
        int2 p0 = g_epack[e];
        float w0 = __int_as_float(p0.y);
        float2 a = __half22float2(
            reinterpret_cast<const __half2*>(g_h2H + (size_t)p0.x * 64)[lane]);
        acc0 = fmaf(w0, a.x, acc0); acc1 = fmaf(w0, a.y, acc1);
    }

    float o0 = fmaf(di, acc0, b2[lane * 2]);
    float o1 = fmaf(di, acc1, b2[lane * 2 + 1]);
    *reinterpret_cast<float2*>(out + (size_t)node * 64 + lane * 2) = make_float2(o0, o1);
}

// ---------------- launch (kernel launches + capture-legal fork/join) ---------
extern "C" void kernel_launch(void* const* d_in, const int* in_sizes, int n_in,
                              void* d_out, int out_size) {
    const float* x  = (const float*)d_in[0];
    const int*   ei = (const int*)d_in[1];     // int32 edge_index (JAX x64 off)
    const float* ew = (const float*)d_in[2];
    const float* W1 = (const float*)d_in[3];
    const float* b1 = (const float*)d_in[4];
    const float* W2 = (const float*)d_in[5];
    const float* b2 = (const float*)d_in[6];
    float*       out = (float*)d_out;

    int n = in_sizes[0] / 128;
    int e = in_sizes[2];
    int nb = (n + 1023) / 1024;

    // one-time handles (no device memory; created on first, non-captured call)
    static cudaStream_t s2 = nullptr;
    static cudaEvent_t ev_fork = nullptr, ev_join = nullptr;
    if (!s2) {
        cudaStreamCreateWithFlags(&s2, cudaStreamNonBlocking);
        cudaEventCreateWithFlags(&ev_fork, cudaEventDisableTiming);
        cudaEventCreateWithFlags(&ev_join, cudaEventDisableTiming);
    }

    // fork: gemm1 (depends only on inputs) runs concurrently with CSR build
    cudaEventRecord(ev_fork, 0);
    cudaStreamWaitEvent(s2, ev_fork, 0);
    gemm1_kernel<<<(n + 127) / 128, 128, 0, s2>>>(n, x, W1);

    // CSR build on origin stream
    init_kernel<<<(n + 255) / 256, 256>>>(n, e);
    hist_kernel<<<(e + 255) / 256, 256>>>(e, ei, ew);
    scan_lookback<<<nb, 256>>>(n);             // single-pass scan + cnt + dinv
    scatter_kernel<<<(e + 255) / 256, 256>>>(e, ei, ew);

    // join: agg1 needs both CSR and g_hH
    cudaEventRecord(ev_join, s2);
    cudaStreamWaitEvent(0, ev_join, 0);

    agg1_kernel<<<(2 * n + 7) / 8, 256>>>(n, b1);   // 2 warps per node
    gemm2_kernel<<<(n + 127) / 128, 128>>>(n, W2);
    agg2_kernel<<<(n + 7) / 8, 256>>>(n, b2, out);
}

// round 16
// speedup vs baseline: 1.0980x; 1.0980x over previous
#include <cuda_runtime.h>
#include <cuda_fp16.h>
#include <cstdint>

// Problem capacities (from reference: N=100000, E=1600000, 128->128->64)
#define MAXN 100000
#define MAXE 1600000

// ---------------- scratch (__device__ globals, 256B-aligned for vector ops) --
__device__ __align__(256) unsigned long long g_hist64[MAXN]; // {cnt:32, deg_fx24:32}
__device__ __align__(256) float  g_dinv[MAXN];
__device__ __align__(256) int    g_rank[MAXE];              // within-bucket rank
__device__ __align__(256) int    g_off[MAXN + 2];
__device__ __align__(256) unsigned long long g_bstate[256]; // lookback states
__device__ __align__(256) int2   g_epack[MAXE];             // {src, bits(w*dinv[src])}
__device__ __align__(256) __half g_hH [(size_t)MAXN * 128]; // x @ W1   (fp16)
__device__ __align__(256) __half g_h2H[(size_t)MAXN * 64];  // agg1+gemm2 out (fp16)

// ---------------- init: deg=1 (self loop, fixed-point 2^24), counters=0 ------
__global__ void init_kernel(int n, int e) {
    int i = blockIdx.x * blockDim.x + threadIdx.x;
    if (i == 0) g_off[n] = e;
    if (i < 256) g_bstate[i] = 0ULL;
    if (i < n) g_hist64[i] = (unsigned long long)(1u << 24); // deg=1.0 fx24, cnt=0
}

// ---------------- fused degree+count histogram + rank assignment -------------
// edge_index is int32 (JAX default x64-disabled downcasts jnp.int64 -> int32).
// The atomic return's high word is this edge's within-bucket rank.
__global__ void hist_kernel(int e, const int* __restrict__ ei,
                            const float* __restrict__ ew) {
    int i = blockIdx.x * blockDim.x + threadIdx.x;
    if (i >= e) return;
    int c = ei[e + i];                         // col = ei[1][i]
    unsigned wfx = __float2uint_rn(ew[i] * 16777216.0f);   // w * 2^24
    unsigned long long old =
        atomicAdd(&g_hist64[c], (1ULL << 32) | (unsigned long long)wfx);
    g_rank[i] = (int)(old >> 32);
}

// ---------------- single-pass scan, warp-parallel decoupled lookback ---------
// 98 blocks x 256 thr; 1024 elements/block; one wave (98 <= 148 SMs).
// Unpacks hist64 -> dinv.
__global__ __launch_bounds__(256) void scan_lookback(int n) {
    __shared__ int wsum[8];
    __shared__ int s_prefix;
    int t = threadIdx.x, lane = t & 31, w = t >> 5;
    int bid = blockIdx.x;
    int base = bid * 1024 + t * 4;

    int v[4];
#pragma unroll
    for (int j = 0; j < 4; j++) {
        int idx = base + j;
        if (idx < n) {
            unsigned long long hv = g_hist64[idx];
            v[j] = (int)(hv >> 32);
            g_dinv[idx] = rsqrtf((float)(unsigned)hv * 5.9604644775390625e-8f); // 2^-24
        } else v[j] = 0;
    }
    int tsum = v[0] + v[1] + v[2] + v[3];

    int sc = tsum;
#pragma unroll
    for (int d = 1; d < 32; d <<= 1) {
        int u = __shfl_up_sync(~0u, sc, d);
        if (lane >= d) sc += u;
    }
    if (lane == 31) wsum[w] = sc;
    __syncthreads();
    if (w == 0) {
        int s = (lane < 8) ? wsum[lane] : 0;
#pragma unroll
        for (int d = 1; d < 8; d <<= 1) {
            int u = __shfl_up_sync(~0u, s, d);
            if (lane >= d) s += u;
        }
        if (lane < 8) wsum[lane] = s;
    }
    __syncthreads();
    int total = wsum[7];

    if (w == 0) {
        if (bid == 0) {
            if (lane == 0) {
                atomicExch(&g_bstate[0], (2ULL << 32) | (unsigned)total);
                s_prefix = 0;
            }
        } else {
            if (lane == 0)
                atomicExch(&g_bstate[bid], (1ULL << 32) | (unsigned)total);
            __syncwarp();
            int pre = 0;
            int p = bid - 1;
            while (true) {
                int idx = p - lane;
                unsigned long long st = (idx >= 0)
                    ? atomicAdd(&g_bstate[idx], 0ULL) : (2ULL << 32);
                unsigned flag = (unsigned)(st >> 32);
                unsigned pm = __ballot_sync(~0u, flag == 2);
                unsigned zm = __ballot_sync(~0u, flag == 0);
                int firstP = pm ? (__ffs(pm) - 1) : 32;
                unsigned before = (firstP < 32) ? ((1u << firstP) - 1u) : ~0u;
                if (zm & before) continue;
                int s;
                if (firstP < 32) {
                    s = (lane <= firstP) ? (int)(unsigned)st : 0;
                } else {
                    if (zm) continue;
                    s = (int)(unsigned)st;
                }
#pragma unroll
                for (int d = 16; d > 0; d >>= 1) s += __shfl_down_sync(~0u, s, d);
                s = __shfl_sync(~0u, s, 0);
                pre += s;
                if (firstP < 32) break;
                p -= 32;
            }
            if (lane == 0) {
                atomicExch(&g_bstate[bid], (2ULL << 32) | (unsigned)(pre + total));
                s_prefix = pre;
            }
        }
    }
    __syncthreads();

    int run = s_prefix + ((w > 0) ? wsum[w - 1] : 0) + (sc - tsum);
#pragma unroll
    for (int j = 0; j < 4; j++) {
        int idx = base + j;
        if (idx < n) g_off[idx] = run;
        run += v[j];
    }
}

// ---------------- scatter edges into CSR buckets (atomic-free) ---------------
__global__ void scatter_kernel(int e, const int* __restrict__ ei,
                               const float* __restrict__ ew) {
    int i = blockIdx.x * blockDim.x + threadIdx.x;
    if (i >= e) return;
    int r = ei[i];
    int c = ei[e + i];
    int pos = g_off[c] + g_rank[i];
    float sw = ew[i] * g_dinv[r];              // w * d_src^{-1/2}
    g_epack[pos] = make_int2(r, __float_as_int(sw));
}

// ---------------- tf32 helpers ------------------------------------------------
__device__ __forceinline__ uint32_t f2tf(float x) {
    uint32_t r;
    asm("cvt.rna.tf32.f32 %0, %1;" : "=r"(r) : "f"(x));
    return r;
}

__device__ __forceinline__ void mma_tf32(float* c, const uint32_t* a,
                                         uint32_t b0, uint32_t b1) {
    asm volatile(
        "mma.sync.aligned.m16n8k8.row.col.f32.tf32.tf32.f32 "
        "{%0,%1,%2,%3}, {%4,%5,%6,%7}, {%8,%9}, {%0,%1,%2,%3};\n"
        : "+f"(c[0]), "+f"(c[1]), "+f"(c[2]), "+f"(c[3])
        : "r"(a[0]), "r"(a[1]), "r"(a[2]), "r"(a[3]), "r"(b0), "r"(b1));
}

// ---------------- gemm1: g_hH = x @ W1 (tf32, direct-LDG A path) --------------
__global__ __launch_bounds__(128) void gemm1_kernel(int n, const float* __restrict__ X,
                                                    const float* __restrict__ W) {
    constexpr int K = 128, OC = 128, KC = 32, OCP = OC + 4, NT = OC / 8;
    __shared__ __align__(16) uint32_t Ws[KC * OCP];

    int tid = threadIdx.x;
    int warp = tid >> 5;
    int lane = tid & 31;
    int g  = lane >> 2;
    int tg = lane & 3;
    int rbase = blockIdx.x * 128 + warp * 32;

    float acc[2][NT][4];
#pragma unroll
    for (int t = 0; t < 2; t++)
#pragma unroll
        for (int nt = 0; nt < NT; nt++)
#pragma unroll
            for (int j = 0; j < 4; j++) acc[t][nt][j] = 0.f;

    int ra[2], rb[2];
#pragma unroll
    for (int t = 0; t < 2; t++) {
        ra[t] = min(rbase + t * 16 + g,     n - 1);
        rb[t] = min(rbase + t * 16 + g + 8, n - 1);
    }

    for (int kc = 0; kc < K; kc += KC) {
        for (int i = tid; i < KC * OC / 4; i += 128) {
            int kk = i / (OC / 4);
            int cc = i % (OC / 4);
            float4 v = reinterpret_cast<const float4*>(W + (size_t)(kc + kk) * OC)[cc];
            uint4 tv = make_uint4(f2tf(v.x), f2tf(v.y), f2tf(v.z), f2tf(v.w));
            *reinterpret_cast<uint4*>(&Ws[kk * OCP + cc * 4]) = tv;
        }
        __syncthreads();

#pragma unroll
        for (int ks = 0; ks < KC; ks += 8) {
            int k0 = kc + ks;
            uint32_t a[2][4];
#pragma unroll
            for (int t = 0; t < 2; t++) {
                a[t][0] = f2tf(X[(size_t)ra[t] * K + k0 + tg]);
                a[t][1] = f2tf(X[(size_t)rb[t] * K + k0 + tg]);
                a[t][2] = f2tf(X[(size_t)ra[t] * K + k0 + tg + 4]);
                a[t][3] = f2tf(X[(size_t)rb[t] * K + k0 + tg + 4]);
            }
#pragma unroll
            for (int nt = 0; nt < NT; nt++) {
                uint32_t b0 = Ws[(ks + tg)     * OCP + nt * 8 + g];
                uint32_t b1 = Ws[(ks + tg + 4) * OCP + nt * 8 + g];
                mma_tf32(acc[0][nt], a[0], b0, b1);
                mma_tf32(acc[1][nt], a[1], b0, b1);
            }
        }
        __syncthreads();
    }

#pragma unroll
    for (int t = 0; t < 2; t++) {
        int r0 = rbase + t * 16 + g;
        int r1 = r0 + 8;
#pragma unroll
        for (int nt = 0; nt < NT; nt++) {
            int col = nt * 8 + 2 * tg;
            if (r0 < n)
                *reinterpret_cast<__half2*>(g_hH + (size_t)r0 * OC + col) =
                    __floats2half2_rn(acc[t][nt][0], acc[t][nt][1]);
            if (r1 < n)
                *reinterpret_cast<__half2*>(g_hH + (size_t)r1 * OC + col) =
                    __floats2half2_rn(acc[t][nt][2], acc[t][nt][3]);
        }
    }
}

// ---------------- FUSED agg1 + gemm2 ------------------------------------------
// Block = 128 nodes, 256 thr (8 warps). Phase A: each warp aggregates 16 nodes
// (relu(agg+b1)) into a 128x132 fp32 smem tile. Phase B: tf32 MMA tile @ W2
// -> g_h2H (fp16). Eliminates the 102MB h1 gmem roundtrip.
// Dynamic smem: As 128*132*4 = 67584 B + Ws 32*68*4 = 8704 B = 76288 B.
#define FUSED_SMEM (128 * 132 * 4 + 32 * 68 * 4)
__global__ __launch_bounds__(256) void fused_agg1_gemm2(int n,
                                                        const float* __restrict__ b1,
                                                        const float* __restrict__ W2) {
    extern __shared__ __align__(16) char smem[];
    float*    As = reinterpret_cast<float*>(smem);                // [128][132]
    uint32_t* Ws = reinterpret_cast<uint32_t*>(smem + 128 * 132 * 4); // [32][68]

    int tid  = threadIdx.x;
    int warp = tid >> 5;
    int lane = tid & 31;
    int rbase = blockIdx.x * 128;

    // ---- Phase A: aggregate 16 nodes per warp into As ----
    float4 b1v = reinterpret_cast<const float4*>(b1)[lane];  // feats lane*4..+3
    for (int i = 0; i < 16; i++) {
        int rloc = warp * 16 + i;
        int node = rbase + rloc;
        float* dst = As + rloc * 132 + lane * 4;
        if (node >= n) {
            *reinterpret_cast<float4*>(dst) = make_float4(0.f, 0.f, 0.f, 0.f);
            continue;
        }
        float di = g_dinv[node];
        uint2 raw = reinterpret_cast<const uint2*>(g_hH + (size_t)node * 128)[lane];
        float2 f01 = __half22float2(*reinterpret_cast<__half2*>(&raw.x));
        float2 f23 = __half22float2(*reinterpret_cast<__half2*>(&raw.y));
        float a0 = di * f01.x, a1 = di * f01.y, a2 = di * f23.x, a3 = di * f23.y;

        int e0 = g_off[node];
        int e1 = g_off[node + 1];
        int e = e0;
        for (; e + 2 <= e1; e += 2) {
            int2 p0 = g_epack[e];
            int2 p1 = g_epack[e + 1];
            float w0 = __int_as_float(p0.y);
            float w1 = __int_as_float(p1.y);
            uint2 r0 = reinterpret_cast<const uint2*>(g_hH + (size_t)p0.x * 128)[lane];
            uint2 r1 = reinterpret_cast<const uint2*>(g_hH + (size_t)p1.x * 128)[lane];
            float2 x01 = __half22float2(*reinterpret_cast<__half2*>(&r0.x));
            float2 x23 = __half22float2(*reinterpret_cast<__half2*>(&r0.y));
            float2 y01 = __half22float2(*reinterpret_cast<__half2*>(&r1.x));
            float2 y23 = __half22float2(*reinterpret_cast<__half2*>(&r1.y));
            a0 = fmaf(w0, x01.x, a0); a1 = fmaf(w0, x01.y, a1);
            a2 = fmaf(w0, x23.x, a2); a3 = fmaf(w0, x23.y, a3);
            a0 = fmaf(w1, y01.x, a0); a1 = fmaf(w1, y01.y, a1);
            a2 = fmaf(w1, y23.x, a2); a3 = fmaf(w1, y23.y, a3);
        }
        if (e < e1) {
            int2 p0 = g_epack[e];
            float w0 = __int_as_float(p0.y);
            uint2 r0 = reinterpret_cast<const uint2*>(g_hH + (size_t)p0.x * 128)[lane];
            float2 x01 = __half22float2(*reinterpret_cast<__half2*>(&r0.x));
            float2 x23 = __half22float2(*reinterpret_cast<__half2*>(&r0.y));
            a0 = fmaf(w0, x01.x, a0); a1 = fmaf(w0, x01.y, a1);
            a2 = fmaf(w0, x23.x, a2); a3 = fmaf(w0, x23.y, a3);
        }
        *reinterpret_cast<float4*>(dst) = make_float4(
            fmaxf(fmaf(di, a0, b1v.x), 0.f), fmaxf(fmaf(di, a1, b1v.y), 0.f),
            fmaxf(fmaf(di, a2, b1v.z), 0.f), fmaxf(fmaf(di, a3, b1v.w), 0.f));
    }
    __syncthreads();

    // ---- Phase B: h2 = As @ W2, tf32 MMA; warp owns 16 rows x 64 cols ----
    constexpr int OC = 64, KC = 32, OCP = OC + 4, NT = OC / 8;
    int g  = lane >> 2;
    int tg = lane & 3;
    float acc[NT][4];
#pragma unroll
    for (int nt = 0; nt < NT; nt++)
#pragma unroll
        for (int j = 0; j < 4; j++) acc[nt][j] = 0.f;

    int rA = warp * 16 + g;
    int rB = rA + 8;

    for (int kc = 0; kc < 128; kc += KC) {
        for (int i = tid; i < KC * OC / 4; i += 256) {
            int kk = i / (OC / 4);
            int cc = i % (OC / 4);
            float4 v = reinterpret_cast<const float4*>(W2 + (size_t)(kc + kk) * OC)[cc];
            uint4 tv = make_uint4(f2tf(v.x), f2tf(v.y), f2tf(v.z), f2tf(v.w));
            *reinterpret_cast<uint4*>(&Ws[kk * OCP + cc * 4]) = tv;
        }
        __syncthreads();

#pragma unroll
        for (int ks = 0; ks < KC; ks += 8) {
            int k0 = kc + ks;
            uint32_t a[4];
            a[0] = f2tf(As[rA * 132 + k0 + tg]);
            a[1] = f2tf(As[rB * 132 + k0 + tg]);
            a[2] = f2tf(As[rA * 132 + k0 + tg + 4]);
            a[3] = f2tf(As[rB * 132 + k0 + tg + 4]);
#pragma unroll
            for (int nt = 0; nt < NT; nt++) {
                uint32_t b0 = Ws[(ks + tg)     * OCP + nt * 8 + g];
                uint32_t b1w = Ws[(ks + tg + 4) * OCP + nt * 8 + g];
                mma_tf32(acc[nt], a, b0, b1w);
            }
        }
        __syncthreads();
    }

    int r0 = rbase + warp * 16 + g;
    int r1 = r0 + 8;
#pragma unroll
    for (int nt = 0; nt < NT; nt++) {
        int col = nt * 8 + 2 * tg;
        if (r0 < n)
            *reinterpret_cast<__half2*>(g_h2H + (size_t)r0 * OC + col) =
                __floats2half2_rn(acc[nt][0], acc[nt][1]);
        if (r1 < n)
            *reinterpret_cast<__half2*>(g_h2H + (size_t)r1 * OC + col) =
                __floats2half2_rn(acc[nt][2], acc[nt][3]);
    }
}

// ---------------- aggregation layer 2: one warp per node (F=64) --------------
__global__ __launch_bounds__(256) void agg2_kernel(int n, const float* __restrict__ b2,
                                                   float* __restrict__ out) {
    int node = blockIdx.x * 8 + (threadIdx.x >> 5);
    if (node >= n) return;
    int lane = threadIdx.x & 31;
    float di = g_dinv[node];

    float2 f = __half22float2(
        reinterpret_cast<const __half2*>(g_h2H + (size_t)node * 64)[lane]);
    float acc0 = di * f.x, acc1 = di * f.y;

    int e0 = g_off[node];
    int e1 = g_off[node + 1];
    int e = e0;
    for (; e + 2 <= e1; e += 2) {
        int2 p0 = g_epack[e];
        int2 p1 = g_epack[e + 1];
        float w0 = __int_as_float(p0.y);
        float w1 = __int_as_float(p1.y);
        float2 a = __half22float2(
            reinterpret_cast<const __half2*>(g_h2H + (size_t)p0.x * 64)[lane]);
        float2 b = __half22float2(
            reinterpret_cast<const __half2*>(g_h2H + (size_t)p1.x * 64)[lane]);
        acc0 = fmaf(w0, a.x, acc0); acc1 = fmaf(w0, a.y, acc1);
        acc0 = fmaf(w1, b.x, acc0); acc1 = fmaf(w1, b.y, acc1);
    }
    if (e < e1) {
        int2 p0 = g_epack[e];
        float w0 = __int_as_float(p0.y);
        float2 a = __half22float2(
            reinterpret_cast<const __half2*>(g_h2H + (size_t)p0.x * 64)[lane]);
        acc0 = fmaf(w0, a.x, acc0); acc1 = fmaf(w0, a.y, acc1);
    }

    float o0 = fmaf(di, acc0, b2[lane * 2]);
    float o1 = fmaf(di, acc1, b2[lane * 2 + 1]);
    *reinterpret_cast<float2*>(out + (size_t)node * 64 + lane * 2) = make_float2(o0, o1);
}

// ---------------- launch (kernel launches + capture-legal fork/join) ---------
extern "C" void kernel_launch(void* const* d_in, const int* in_sizes, int n_in,
                              void* d_out, int out_size) {
    const float* x  = (const float*)d_in[0];
    const int*   ei = (const int*)d_in[1];     // int32 edge_index (JAX x64 off)
    const float* ew = (const float*)d_in[2];
    const float* W1 = (const float*)d_in[3];
    const float* b1 = (const float*)d_in[4];
    const float* W2 = (const float*)d_in[5];
    const float* b2 = (const float*)d_in[6];
    float*       out = (float*)d_out;

    int n = in_sizes[0] / 128;
    int e = in_sizes[2];
    int nb = (n + 1023) / 1024;

    // one-time handles/config (no device memory; first call is not captured)
    static cudaStream_t s2 = nullptr;
    static cudaEvent_t ev_fork = nullptr, ev_join = nullptr;
    if (!s2) {
        cudaStreamCreateWithFlags(&s2, cudaStreamNonBlocking);
        cudaEventCreateWithFlags(&ev_fork, cudaEventDisableTiming);
        cudaEventCreateWithFlags(&ev_join, cudaEventDisableTiming);
        cudaFuncSetAttribute(fused_agg1_gemm2,
                             cudaFuncAttributeMaxDynamicSharedMemorySize, FUSED_SMEM);
    }

    // fork point: s2 branches off the origin stream at the start
    cudaEventRecord(ev_fork, 0);
    cudaStreamWaitEvent(s2, ev_fork, 0);

    // CSR build on origin stream
    init_kernel<<<(n + 255) / 256, 256>>>(n, e);
    hist_kernel<<<(e + 255) / 256, 256>>>(e, ei, ew);
    scan_lookback<<<nb, 256>>>(n);             // scan + dinv
    scatter_kernel<<<(e + 255) / 256, 256>>>(e, ei, ew);

    // gemm1 on s2 (graph-parallel with CSR build; depends only on inputs)
    gemm1_kernel<<<(n + 127) / 128, 128, 0, s2>>>(n, x, W1);

    // join: fused kernel needs both CSR and g_hH
    cudaEventRecord(ev_join, s2);
    cudaStreamWaitEvent(0, ev_join, 0);

    fused_agg1_gemm2<<<(n + 127) / 128, 256, FUSED_SMEM>>>(n, b1, W2);
    agg2_kernel<<<(n + 7) / 8, 256>>>(n, b2, out);
}

// round 17
// speedup vs baseline: 1.0984x; 1.0003x over previous
#include <cuda_runtime.h>
#include <cuda_fp16.h>
#include <cstdint>

// Problem capacities (from reference: N=100000, E=1600000, 128->128->64)
#define MAXN 100000
#define MAXE 1600000

// ---------------- scratch (__device__ globals, 256B-aligned for vector ops) --
__device__ __align__(256) unsigned long long g_hist64[MAXN]; // {cnt:32, deg_fx24:32}
__device__ __align__(256) float  g_dinv[MAXN];
__device__ __align__(256) unsigned g_rankc[MAXE];           // {rank:15, col:17}
__device__ __align__(256) int    g_off[MAXN + 2];
__device__ __align__(256) unsigned long long g_bstate[256]; // lookback states
__device__ __align__(256) int2   g_epack[MAXE];             // {src, bits(w)}
__device__ __align__(256) __half g_hH [(size_t)MAXN * 128]; // dinv .* (x @ W1)  (fp16)
__device__ __align__(256) __half g_h2H[(size_t)MAXN * 64];  // dinv .* (agg1@W2) (fp16)

// ---------------- init: deg=1 (self loop, fixed-point 2^24), counters=0 ------
__global__ void init_kernel(int n, int e) {
    int i = blockIdx.x * blockDim.x + threadIdx.x;
    if (i == 0) g_off[n] = e;
    if (i < 256) g_bstate[i] = 0ULL;
    if (i < n) g_hist64[i] = (unsigned long long)(1u << 24); // deg=1.0 fx24, cnt=0
}

// ---------------- fused degree+count histogram + (rank,col) pack -------------
// edge_index is int32 (JAX default x64-disabled downcasts jnp.int64 -> int32).
// Atomic return's high word = this edge's within-bucket rank (< 2^15 for this
// random graph: in-degree ~ Poisson(16)). col < 2^17.
__global__ void hist_kernel(int e, const int* __restrict__ ei,
                            const float* __restrict__ ew) {
    int i = blockIdx.x * blockDim.x + threadIdx.x;
    if (i >= e) return;
    int c = ei[e + i];                         // col = ei[1][i]
    unsigned wfx = __float2uint_rn(ew[i] * 16777216.0f);   // w * 2^24
    unsigned long long old =
        atomicAdd(&g_hist64[c], (1ULL << 32) | (unsigned long long)wfx);
    g_rankc[i] = ((unsigned)(old >> 32) << 17) | (unsigned)c;
}

// ---------------- single-pass scan, warp-parallel decoupled lookback ---------
// 98 blocks x 256 thr; 1024 elements/block; one wave (98 <= 148 SMs).
// Unpacks hist64 -> dinv.
__global__ __launch_bounds__(256) void scan_lookback(int n) {
    __shared__ int wsum[8];
    __shared__ int s_prefix;
    int t = threadIdx.x, lane = t & 31, w = t >> 5;
    int bid = blockIdx.x;
    int base = bid * 1024 + t * 4;

    int v[4];
#pragma unroll
    for (int j = 0; j < 4; j++) {
        int idx = base + j;
        if (idx < n) {
            unsigned long long hv = g_hist64[idx];
            v[j] = (int)(hv >> 32);
            g_dinv[idx] = rsqrtf((float)(unsigned)hv * 5.9604644775390625e-8f); // 2^-24
        } else v[j] = 0;
    }
    int tsum = v[0] + v[1] + v[2] + v[3];

    int sc = tsum;
#pragma unroll
    for (int d = 1; d < 32; d <<= 1) {
        int u = __shfl_up_sync(~0u, sc, d);
        if (lane >= d) sc += u;
    }
    if (lane == 31) wsum[w] = sc;
    __syncthreads();
    if (w == 0) {
        int s = (lane < 8) ? wsum[lane] : 0;
#pragma unroll
        for (int d = 1; d < 8; d <<= 1) {
            int u = __shfl_up_sync(~0u, s, d);
            if (lane >= d) s += u;
        }
        if (lane < 8) wsum[lane] = s;
    }
    __syncthreads();
    int total = wsum[7];

    if (w == 0) {
        if (bid == 0) {
            if (lane == 0) {
                atomicExch(&g_bstate[0], (2ULL << 32) | (unsigned)total);
                s_prefix = 0;
            }
        } else {
            if (lane == 0)
                atomicExch(&g_bstate[bid], (1ULL << 32) | (unsigned)total);
            __syncwarp();
            int pre = 0;
            int p = bid - 1;
            while (true) {
                int idx = p - lane;
                unsigned long long st = (idx >= 0)
                    ? atomicAdd(&g_bstate[idx], 0ULL) : (2ULL << 32);
                unsigned flag = (unsigned)(st >> 32);
                unsigned pm = __ballot_sync(~0u, flag == 2);
                unsigned zm = __ballot_sync(~0u, flag == 0);
                int firstP = pm ? (__ffs(pm) - 1) : 32;
                unsigned before = (firstP < 32) ? ((1u << firstP) - 1u) : ~0u;
                if (zm & before) continue;
                int s;
                if (firstP < 32) {
                    s = (lane <= firstP) ? (int)(unsigned)st : 0;
                } else {
                    if (zm) continue;
                    s = (int)(unsigned)st;
                }
#pragma unroll
                for (int d = 16; d > 0; d >>= 1) s += __shfl_down_sync(~0u, s, d);
                s = __shfl_sync(~0u, s, 0);
                pre += s;
                if (firstP < 32) break;
                p -= 32;
            }
            if (lane == 0) {
                atomicExch(&g_bstate[bid], (2ULL << 32) | (unsigned)(pre + total));
                s_prefix = pre;
            }
        }
    }
    __syncthreads();

    int run = s_prefix + ((w > 0) ? wsum[w - 1] : 0) + (sc - tsum);
#pragma unroll
    for (int j = 0; j < 4; j++) {
        int idx = base + j;
        if (idx < n) g_off[idx] = run;
        run += v[j];
    }
}

// ---------------- scatter edges into CSR buckets (atomic-free, no gathers) ---
__global__ void scatter_kernel(int e, const int* __restrict__ ei,
                               const float* __restrict__ ew) {
    int i = blockIdx.x * blockDim.x + threadIdx.x;
    if (i >= e) return;
    unsigned rc = g_rankc[i];
    int c    = (int)(rc & 0x1FFFFu);
    int rank = (int)(rc >> 17);
    int pos = g_off[c] + rank;
    g_epack[pos] = make_int2(ei[i], __float_as_int(ew[i]));  // {src, w}
}

// ---------------- scale: g_hH[i] *= dinv[i] (one warp per node) --------------
// Runs on s2 after {gemm1, scan}; overlaps scatter. 50MB streaming.
__global__ __launch_bounds__(256) void scale_h_kernel(int n) {
    int gt = blockIdx.x * 256 + threadIdx.x;
    int node = gt >> 5;
    if (node >= n) return;
    int lane = gt & 31;
    float di = g_dinv[node];
    uint2* p = reinterpret_cast<uint2*>(g_hH + (size_t)node * 128) + lane;
    uint2 raw = *p;
    float2 f01 = __half22float2(*reinterpret_cast<__half2*>(&raw.x));
    float2 f23 = __half22float2(*reinterpret_cast<__half2*>(&raw.y));
    __half2 h01 = __floats2half2_rn(di * f01.x, di * f01.y);
    __half2 h23 = __floats2half2_rn(di * f23.x, di * f23.y);
    *p = make_uint2(*reinterpret_cast<uint32_t*>(&h01),
                    *reinterpret_cast<uint32_t*>(&h23));
}

// ---------------- tf32 helpers ------------------------------------------------
__device__ __forceinline__ uint32_t f2tf(float x) {
    uint32_t r;
    asm("cvt.rna.tf32.f32 %0, %1;" : "=r"(r) : "f"(x));
    return r;
}

__device__ __forceinline__ void mma_tf32(float* c, const uint32_t* a,
                                         uint32_t b0, uint32_t b1) {
    asm volatile(
        "mma.sync.aligned.m16n8k8.row.col.f32.tf32.tf32.f32 "
        "{%0,%1,%2,%3}, {%4,%5,%6,%7}, {%8,%9}, {%0,%1,%2,%3};\n"
        : "+f"(c[0]), "+f"(c[1]), "+f"(c[2]), "+f"(c[3])
        : "r"(a[0]), "r"(a[1]), "r"(a[2]), "r"(a[3]), "r"(b0), "r"(b1));
}

// ---------------- gemm1: g_hH = x @ W1 (tf32, direct-LDG A path) --------------
__global__ __launch_bounds__(128) void gemm1_kernel(int n, const float* __restrict__ X,
                                                    const float* __restrict__ W) {
    constexpr int K = 128, OC = 128, KC = 32, OCP = OC + 4, NT = OC / 8;
    __shared__ __align__(16) uint32_t Ws[KC * OCP];

    int tid = threadIdx.x;
    int warp = tid >> 5;
    int lane = tid & 31;
    int g  = lane >> 2;
    int tg = lane & 3;
    int rbase = blockIdx.x * 128 + warp * 32;

    float acc[2][NT][4];
#pragma unroll
    for (int t = 0; t < 2; t++)
#pragma unroll
        for (int nt = 0; nt < NT; nt++)
#pragma unroll
            for (int j = 0; j < 4; j++) acc[t][nt][j] = 0.f;

    int ra[2], rb[2];
#pragma unroll
    for (int t = 0; t < 2; t++) {
        ra[t] = min(rbase + t * 16 + g,     n - 1);
        rb[t] = min(rbase + t * 16 + g + 8, n - 1);
    }

    for (int kc = 0; kc < K; kc += KC) {
        for (int i = tid; i < KC * OC / 4; i += 128) {
            int kk = i / (OC / 4);
            int cc = i % (OC / 4);
            float4 v = reinterpret_cast<const float4*>(W + (size_t)(kc + kk) * OC)[cc];
            uint4 tv = make_uint4(f2tf(v.x), f2tf(v.y), f2tf(v.z), f2tf(v.w));
            *reinterpret_cast<uint4*>(&Ws[kk * OCP + cc * 4]) = tv;
        }
        __syncthreads();

#pragma unroll
        for (int ks = 0; ks < KC; ks += 8) {
            int k0 = kc + ks;
            uint32_t a[2][4];
#pragma unroll
            for (int t = 0; t < 2; t++) {
                a[t][0] = f2tf(X[(size_t)ra[t] * K + k0 + tg]);
                a[t][1] = f2tf(X[(size_t)rb[t] * K + k0 + tg]);
                a[t][2] = f2tf(X[(size_t)ra[t] * K + k0 + tg + 4]);
                a[t][3] = f2tf(X[(size_t)rb[t] * K + k0 + tg + 4]);
            }
#pragma unroll
            for (int nt = 0; nt < NT; nt++) {
                uint32_t b0 = Ws[(ks + tg)     * OCP + nt * 8 + g];
                uint32_t b1 = Ws[(ks + tg + 4) * OCP + nt * 8 + g];
                mma_tf32(acc[0][nt], a[0], b0, b1);
                mma_tf32(acc[1][nt], a[1], b0, b1);
            }
        }
        __syncthreads();
    }

#pragma unroll
    for (int t = 0; t < 2; t++) {
        int r0 = rbase + t * 16 + g;
        int r1 = r0 + 8;
#pragma unroll
        for (int nt = 0; nt < NT; nt++) {
            int col = nt * 8 + 2 * tg;
            if (r0 < n)
                *reinterpret_cast<__half2*>(g_hH + (size_t)r0 * OC + col) =
                    __floats2half2_rn(acc[t][nt][0], acc[t][nt][1]);
            if (r1 < n)
                *reinterpret_cast<__half2*>(g_hH + (size_t)r1 * OC + col) =
                    __floats2half2_rn(acc[t][nt][2], acc[t][nt][3]);
        }
    }
}

// ---------------- FUSED agg1 + gemm2 ------------------------------------------
// Block = 128 nodes, 256 thr (8 warps). Phase A: relu(d_c*(sum w*h'[src] +
// h'[c]) + b1) into a 128x132 fp32 smem tile (h' = dinv.*h). Phase B: tf32 MMA
// tile @ W2, epilogue scales rows by dinv -> g_h2H (fp16).
#define FUSED_SMEM (128 * 132 * 4 + 32 * 68 * 4)
__global__ __launch_bounds__(256) void fused_agg1_gemm2(int n,
                                                        const float* __restrict__ b1,
                                                        const float* __restrict__ W2) {
    extern __shared__ __align__(16) char smem[];
    float*    As = reinterpret_cast<float*>(smem);                // [128][132]
    uint32_t* Ws = reinterpret_cast<uint32_t*>(smem + 128 * 132 * 4); // [32][68]

    int tid  = threadIdx.x;
    int warp = tid >> 5;
    int lane = tid & 31;
    int rbase = blockIdx.x * 128;

    // ---- Phase A: aggregate 16 nodes per warp into As ----
    float4 b1v = reinterpret_cast<const float4*>(b1)[lane];  // feats lane*4..+3
    for (int i = 0; i < 16; i++) {
        int rloc = warp * 16 + i;
        int node = rbase + rloc;
        float* dst = As + rloc * 132 + lane * 4;
        if (node >= n) {
            *reinterpret_cast<float4*>(dst) = make_float4(0.f, 0.f, 0.f, 0.f);
            continue;
        }
        float di = g_dinv[node];
        uint2 raw = reinterpret_cast<const uint2*>(g_hH + (size_t)node * 128)[lane];
        float2 f01 = __half22float2(*reinterpret_cast<__half2*>(&raw.x));
        float2 f23 = __half22float2(*reinterpret_cast<__half2*>(&raw.y));
        float a0 = f01.x, a1 = f01.y, a2 = f23.x, a3 = f23.y;   // self: h'[c]

        int e0 = g_off[node];
        int e1 = g_off[node + 1];
        int e = e0;
        for (; e + 2 <= e1; e += 2) {
            int2 p0 = g_epack[e];
            int2 p1 = g_epack[e + 1];
            float w0 = __int_as_float(p0.y);
            float w1 = __int_as_float(p1.y);
            uint2 r0 = reinterpret_cast<const uint2*>(g_hH + (size_t)p0.x * 128)[lane];
            uint2 r1 = reinterpret_cast<const uint2*>(g_hH + (size_t)p1.x * 128)[lane];
            float2 x01 = __half22float2(*reinterpret_cast<__half2*>(&r0.x));
            float2 x23 = __half22float2(*reinterpret_cast<__half2*>(&r0.y));
            float2 y01 = __half22float2(*reinterpret_cast<__half2*>(&r1.x));
            float2 y23 = __half22float2(*reinterpret_cast<__half2*>(&r1.y));
            a0 = fmaf(w0, x01.x, a0); a1 = fmaf(w0, x01.y, a1);
            a2 = fmaf(w0, x23.x, a2); a3 = fmaf(w0, x23.y, a3);
            a0 = fmaf(w1, y01.x, a0); a1 = fmaf(w1, y01.y, a1);
            a2 = fmaf(w1, y23.x, a2); a3 = fmaf(w1, y23.y, a3);
        }
        if (e < e1) {
            int2 p0 = g_epack[e];
            float w0 = __int_as_float(p0.y);
            uint2 r0 = reinterpret_cast<const uint2*>(g_hH + (size_t)p0.x * 128)[lane];
            float2 x01 = __half22float2(*reinterpret_cast<__half2*>(&r0.x));
            float2 x23 = __half22float2(*reinterpret_cast<__half2*>(&r0.y));
            a0 = fmaf(w0, x01.x, a0); a1 = fmaf(w0, x01.y, a1);
            a2 = fmaf(w0, x23.x, a2); a3 = fmaf(w0, x23.y, a3);
        }
        *reinterpret_cast<float4*>(dst) = make_float4(
            fmaxf(fmaf(di, a0, b1v.x), 0.f), fmaxf(fmaf(di, a1, b1v.y), 0.f),
            fmaxf(fmaf(di, a2, b1v.z), 0.f), fmaxf(fmaf(di, a3, b1v.w), 0.f));
    }
    __syncthreads();

    // ---- Phase B: h2' = dinv .* (As @ W2), tf32 MMA; warp: 16 rows x 64 cols --
    constexpr int OC = 64, KC = 32, OCP = OC + 4, NT = OC / 8;
    int g  = lane >> 2;
    int tg = lane & 3;
    float acc[NT][4];
#pragma unroll
    for (int nt = 0; nt < NT; nt++)
#pragma unroll
        for (int j = 0; j < 4; j++) acc[nt][j] = 0.f;

    int rA = warp * 16 + g;
    int rB = rA + 8;

    for (int kc = 0; kc < 128; kc += KC) {
        for (int i = tid; i < KC * OC / 4; i += 256) {
            int kk = i / (OC / 4);
            int cc = i % (OC / 4);
            float4 v = reinterpret_cast<const float4*>(W2 + (size_t)(kc + kk) * OC)[cc];
            uint4 tv = make_uint4(f2tf(v.x), f2tf(v.y), f2tf(v.z), f2tf(v.w));
            *reinterpret_cast<uint4*>(&Ws[kk * OCP + cc * 4]) = tv;
        }
        __syncthreads();

#pragma unroll
        for (int ks = 0; ks < KC; ks += 8) {
            int k0 = kc + ks;
            uint32_t a[4];
            a[0] = f2tf(As[rA * 132 + k0 + tg]);
            a[1] = f2tf(As[rB * 132 + k0 + tg]);
            a[2] = f2tf(As[rA * 132 + k0 + tg + 4]);
            a[3] = f2tf(As[rB * 132 + k0 + tg + 4]);
#pragma unroll
            for (int nt = 0; nt < NT; nt++) {
                uint32_t b0 = Ws[(ks + tg)     * OCP + nt * 8 + g];
                uint32_t b1w = Ws[(ks + tg + 4) * OCP + nt * 8 + g];
                mma_tf32(acc[nt], a, b0, b1w);
            }
        }
        __syncthreads();
    }

    int r0 = rbase + warp * 16 + g;
    int r1 = r0 + 8;
    float d0 = (r0 < n) ? g_dinv[r0] : 0.f;    // fold dinv into epilogue
    float d1 = (r1 < n) ? g_dinv[r1] : 0.f;
#pragma unroll
    for (int nt = 0; nt < NT; nt++) {
        int col = nt * 8 + 2 * tg;
        if (r0 < n)
            *reinterpret_cast<__half2*>(g_h2H + (size_t)r0 * OC + col) =
                __floats2half2_rn(d0 * acc[nt][0], d0 * acc[nt][1]);
        if (r1 < n)
            *reinterpret_cast<__half2*>(g_h2H + (size_t)r1 * OC + col) =
                __floats2half2_rn(d1 * acc[nt][2], d1 * acc[nt][3]);
    }
}

// ---------------- aggregation layer 2: one warp per node (F=64) --------------
// out[c] = d_c * (sum w*h2'[src] + h2'[c]) + b2    (h2' = dinv .* h2)
__global__ __launch_bounds__(256) void agg2_kernel(int n, const float* __restrict__ b2,
                                                   float* __restrict__ out) {
    int node = blockIdx.x * 8 + (threadIdx.x >> 5);
    if (node >= n) return;
    int lane = threadIdx.x & 31;
    float di = g_dinv[node];

    float2 f = __half22float2(
        reinterpret_cast<const __half2*>(g_h2H + (size_t)node * 64)[lane]);
    float acc0 = f.x, acc1 = f.y;              // self: h2'[c]

    int e0 = g_off[node];
    int e1 = g_off[node + 1];
    int e = e0;
    for (; e + 2 <= e1; e += 2) {
        int2 p0 = g_epack[e];
        int2 p1 = g_epack[e + 1];
        float w0 = __int_as_float(p0.y);
        float w1 = __int_as_float(p1.y);
        float2 a = __half22float2(
            reinterpret_cast<const __half2*>(g_h2H + (size_t)p0.x * 64)[lane]);
        float2 b = __half22float2(
            reinterpret_cast<const __half2*>(g_h2H + (size_t)p1.x * 64)[lane]);
        acc0 = fmaf(w0, a.x, acc0); acc1 = fmaf(w0, a.y, acc1);
        acc0 = fmaf(w1, b.x, acc0); acc1 = fmaf(w1, b.y, acc1);
    }
    if (e < e1) {
        int2 p0 = g_epack[e];
        float w0 = __int_as_float(p0.y);
        float2 a = __half22float2(
            reinterpret_cast<const __half2*>(g_h2H + (size_t)p0.x * 64)[lane]);
        acc0 = fmaf(w0, a.x, acc0); acc1 = fmaf(w0, a.y, acc1);
    }

    float o0 = fmaf(di, acc0, b2[lane * 2]);
    float o1 = fmaf(di, acc1, b2[lane * 2 + 1]);
    *reinterpret_cast<float2*>(out + (size_t)node * 64 + lane * 2) = make_float2(o0, o1);
}

// ---------------- launch (kernel launches + capture-legal fork/join) ---------
extern "C" void kernel_launch(void* const* d_in, const int* in_sizes, int n_in,
                              void* d_out, int out_size) {
    const float* x  = (const float*)d_in[0];
    const int*   ei = (const int*)d_in[1];     // int32 edge_index (JAX x64 off)
    const float* ew = (const float*)d_in[2];
    const float* W1 = (const float*)d_in[3];
    const float* b1 = (const float*)d_in[4];
    const float* W2 = (const float*)d_in[5];
    const float* b2 = (const float*)d_in[6];
    float*       out = (float*)d_out;

    int n = in_sizes[0] / 128;
    int e = in_sizes[2];
    int nb = (n + 1023) / 1024;

    // one-time handles/config (no device memory; first call is not captured)
    static cudaStream_t s2 = nullptr;
    static cudaEvent_t ev_fork = nullptr, ev_scan = nullptr, ev_join = nullptr;
    if (!s2) {
        cudaStreamCreateWithFlags(&s2, cudaStreamNonBlocking);
        cudaEventCreateWithFlags(&ev_fork, cudaEventDisableTiming);
        cudaEventCreateWithFlags(&ev_scan, cudaEventDisableTiming);
        cudaEventCreateWithFlags(&ev_join, cudaEventDisableTiming);
        cudaFuncSetAttribute(fused_agg1_gemm2,
                             cudaFuncAttributeMaxDynamicSharedMemorySize, FUSED_SMEM);
    }

    // fork point: s2 branches off the origin stream at the start
    cudaEventRecord(ev_fork, 0);
    cudaStreamWaitEvent(s2, ev_fork, 0);

    // CSR build on origin stream
    init_kernel<<<(n + 255) / 256, 256>>>(n, e);
    hist_kernel<<<(e + 255) / 256, 256>>>(e, ei, ew);
    scan_lookback<<<nb, 256>>>(n);             // scan + dinv
    cudaEventRecord(ev_scan, 0);
    scatter_kernel<<<(e + 255) / 256, 256>>>(e, ei, ew);

    // s2: gemm1 (inputs only), then scale by dinv once scan is done.
    // scale_h overlaps scatter on stream 0.
    gemm1_kernel<<<(n + 127) / 128, 128, 0, s2>>>(n, x, W1);
    cudaStreamWaitEvent(s2, ev_scan, 0);
    scale_h_kernel<<<(32 * n + 255) / 256, 256, 0, s2>>>(n);

    // join: fused kernel needs CSR (stream0) and scaled g_hH (s2)
    cudaEventRecord(ev_join, s2);
    cudaStreamWaitEvent(0, ev_join, 0);

    fused_agg1_gemm2<<<(n + 127) / 128, 256, FUSED_SMEM>>>(n, b1, W2);
    agg2_kernel<<<(n + 7) / 8, 256>>>(n, b2, out);
}